// round 1
// baseline (speedup 1.0000x reference)
#include <cuda_runtime.h>
#include <cuda_bf16.h>
#include <cstdint>
#include <math.h>

// Problem constants
#define M_DIM 16384          // B*S = 16*1024
#define K_DIM 4864           // IN_DIM = 256 * 19
#define N_DIM 640            // G*V = 2*320
#define NVARS 320
#define NGROUPS 2
#define CVD   128            // CV_DIM / G
#define OUT_ELEMS (M_DIM * 256)
#define MARGIN 0.02f

// ---------------- scratch (static device globals; no dynamic alloc) ----------------
__device__ __nv_bfloat16 g_Abf[(size_t)M_DIM * K_DIM];   // ~159 MB  A in bf16
__device__ __nv_bfloat16 g_Btbf[(size_t)N_DIM * K_DIM];  // ~6.2 MB  W^T in bf16  [n][k]
__device__ float         g_Wt[(size_t)N_DIM * K_DIM];    // ~12.5 MB W^T in fp32  [n][k]
__device__ float         g_logits[(size_t)M_DIM * N_DIM];// ~42 MB
__device__ int           g_idx[M_DIM * NGROUPS];
__device__ int           g_counts[N_DIM];

// ---------------- kernel 1: convert hidden_states fp32 -> bf16 ----------------
__global__ void conv_a_kernel(const float* __restrict__ A) {
    int i = blockIdx.x * blockDim.x + threadIdx.x;   // one float4 per thread
    // total = M*K/4 = 19,922,944 ; grid sized exactly
    float4 v = reinterpret_cast<const float4*>(A)[i];
    __nv_bfloat162* o = reinterpret_cast<__nv_bfloat162*>(g_Abf) + (size_t)i * 2;
    o[0] = __floats2bfloat162_rn(v.x, v.y);
    o[1] = __floats2bfloat162_rn(v.z, v.w);
}

// ---------------- kernel 2: transpose W [K][N] -> Wt [N][K] (fp32 + bf16) ----------------
__global__ void trans_w_kernel(const float* __restrict__ W) {
    __shared__ float tile[32][33];
    int x = blockIdx.x * 32 + threadIdx.x;  // n index for loads
    int y0 = blockIdx.y * 32;               // k base
    #pragma unroll
    for (int j = threadIdx.y; j < 32; j += 8) {
        tile[j][threadIdx.x] = W[(size_t)(y0 + j) * N_DIM + x];
    }
    __syncthreads();
    #pragma unroll
    for (int j = threadIdx.y; j < 32; j += 8) {
        int n = blockIdx.x * 32 + j;
        int k = y0 + threadIdx.x;
        float val = tile[threadIdx.x][j];
        g_Wt[(size_t)n * K_DIM + k] = val;
        g_Btbf[(size_t)n * K_DIM + k] = __float2bfloat16_rn(val);
    }
}

// ---------------- kernel 3: bf16 GEMM (HMMA m16n8k16), logits = A @ W + b ----------------
// CTA tile 128x128, K-step 32, 256 threads (8 warps: 4 along M x 2 along N, warp tile 32x64)
#define SMEM_PAD 40      // bf16 per row (conflict-free: 20 words, stride pattern covers all banks)
#define SMEM_TILE (128 * SMEM_PAD)

__global__ __launch_bounds__(256) void gemm_kernel(const float* __restrict__ bias) {
    __shared__ __nv_bfloat16 As[2][SMEM_TILE];
    __shared__ __nv_bfloat16 Bs[2][SMEM_TILE];

    const int tid  = threadIdx.x;
    const int cta_m = blockIdx.y * 128;
    const int cta_n = blockIdx.x * 128;
    const int warp = tid >> 5;
    const int lane = tid & 31;
    const int wm = warp >> 1;        // 0..3
    const int wn = warp & 1;         // 0..1
    const int g  = lane >> 2;        // 0..7
    const int t  = lane & 3;         // 0..3

    float acc[2][8][4];
    #pragma unroll
    for (int a = 0; a < 2; a++)
        #pragma unroll
        for (int b = 0; b < 8; b++)
            #pragma unroll
            for (int c = 0; c < 4; c++) acc[a][b][c] = 0.0f;

    uint32_t sA = (uint32_t)__cvta_generic_to_shared(&As[0][0]);
    uint32_t sB = (uint32_t)__cvta_generic_to_shared(&Bs[0][0]);

    const __nv_bfloat16* Ag = g_Abf;
    const __nv_bfloat16* Bg = g_Btbf;

    const int NKT = K_DIM / 32;  // 152

    // stage loader: 8B cp.async, 4 per matrix per thread
    auto load_stage = [&](int buf, int k0) {
        #pragma unroll
        for (int i = 0; i < 4; i++) {
            int c   = tid + 256 * i;
            int row = c >> 3;
            int seg = c & 7;
            const __nv_bfloat16* srcA = Ag + (size_t)(cta_m + row) * K_DIM + k0 + seg * 4;
            uint32_t dstA = sA + (uint32_t)(buf * SMEM_TILE + row * SMEM_PAD + seg * 4) * 2u;
            asm volatile("cp.async.ca.shared.global [%0], [%1], 8;\n" :: "r"(dstA), "l"(srcA));
            const __nv_bfloat16* srcB = Bg + (size_t)(cta_n + row) * K_DIM + k0 + seg * 4;
            uint32_t dstB = sB + (uint32_t)(buf * SMEM_TILE + row * SMEM_PAD + seg * 4) * 2u;
            asm volatile("cp.async.ca.shared.global [%0], [%1], 8;\n" :: "r"(dstB), "l"(srcB));
        }
    };

    load_stage(0, 0);
    asm volatile("cp.async.commit_group;\n");

    int buf = 0;
    for (int kt = 0; kt < NKT; kt++) {
        if (kt + 1 < NKT) {
            load_stage(buf ^ 1, (kt + 1) * 32);
            asm volatile("cp.async.commit_group;\n");
            asm volatile("cp.async.wait_group 1;\n");
        } else {
            asm volatile("cp.async.wait_group 0;\n");
        }
        __syncthreads();

        const uint32_t* As32 = reinterpret_cast<const uint32_t*>(&As[buf][0]);
        const uint32_t* Bs32 = reinterpret_cast<const uint32_t*>(&Bs[buf][0]);

        #pragma unroll
        for (int kk = 0; kk < 2; kk++) {
            const int kw = kk * 8 + t;  // word offset within 20-word row
            uint32_t afr[2][4];
            #pragma unroll
            for (int mt = 0; mt < 2; mt++) {
                int row = wm * 32 + mt * 16 + g;
                afr[mt][0] = As32[row * 20 + kw];
                afr[mt][1] = As32[(row + 8) * 20 + kw];
                afr[mt][2] = As32[row * 20 + kw + 4];
                afr[mt][3] = As32[(row + 8) * 20 + kw + 4];
            }
            uint32_t bfr[8][2];
            #pragma unroll
            for (int nt = 0; nt < 8; nt++) {
                int n = wn * 64 + nt * 8 + g;
                bfr[nt][0] = Bs32[n * 20 + kw];
                bfr[nt][1] = Bs32[n * 20 + kw + 4];
            }
            #pragma unroll
            for (int mt = 0; mt < 2; mt++) {
                #pragma unroll
                for (int nt = 0; nt < 8; nt++) {
                    asm volatile(
                        "mma.sync.aligned.m16n8k16.row.col.f32.bf16.bf16.f32 "
                        "{%0,%1,%2,%3}, {%4,%5,%6,%7}, {%8,%9}, {%0,%1,%2,%3};\n"
                        : "+f"(acc[mt][nt][0]), "+f"(acc[mt][nt][1]),
                          "+f"(acc[mt][nt][2]), "+f"(acc[mt][nt][3])
                        : "r"(afr[mt][0]), "r"(afr[mt][1]), "r"(afr[mt][2]), "r"(afr[mt][3]),
                          "r"(bfr[nt][0]), "r"(bfr[nt][1]));
                }
            }
        }
        __syncthreads();
        buf ^= 1;
    }

    // epilogue: add bias, write logits
    #pragma unroll
    for (int mt = 0; mt < 2; mt++) {
        int row = cta_m + wm * 32 + mt * 16 + g;
        #pragma unroll
        for (int nt = 0; nt < 8; nt++) {
            int col = cta_n + wn * 64 + nt * 8 + 2 * t;
            float2 bv = *reinterpret_cast<const float2*>(bias + col);
            float2 v0 = make_float2(acc[mt][nt][0] + bv.x, acc[mt][nt][1] + bv.y);
            float2 v1 = make_float2(acc[mt][nt][2] + bv.x, acc[mt][nt][3] + bv.y);
            *reinterpret_cast<float2*>(g_logits + (size_t)row * N_DIM + col) = v0;
            *reinterpret_cast<float2*>(g_logits + (size_t)(row + 8) * N_DIM + col) = v1;
        }
    }
}

// ---------------- kernel 4: zero counts ----------------
__global__ void zero_counts_kernel() {
    g_counts[threadIdx.x] = 0;
}

// ---------------- kernel 5: argmax + exact fp32 rescue + histogram ----------------
// one warp per (row, group)
__global__ __launch_bounds__(256) void argmax_kernel(const float* __restrict__ hidden,
                                                     const float* __restrict__ bias) {
    const int lane = threadIdx.x & 31;
    const int gw = blockIdx.x * 8 + (threadIdx.x >> 5);  // 0..32767
    const int r = gw >> 1;
    const int g = gw & 1;
    const float* base = g_logits + (size_t)r * N_DIM + g * NVARS;

    float v[10];
    float bestv = -INFINITY;
    int besti = 0x7fffffff;
    #pragma unroll
    for (int j = 0; j < 10; j++) {
        v[j] = base[lane + 32 * j];
        int idx = lane + 32 * j;
        if (v[j] > bestv) { bestv = v[j]; besti = idx; }   // ascending idx: strict > keeps first
    }
    // warp reduce (value, index), lower index wins ties
    #pragma unroll
    for (int off = 16; off > 0; off >>= 1) {
        float ov = __shfl_down_sync(0xffffffffu, bestv, off);
        int   oi = __shfl_down_sync(0xffffffffu, besti, off);
        if (ov > bestv || (ov == bestv && oi < besti)) { bestv = ov; besti = oi; }
    }
    bestv = __shfl_sync(0xffffffffu, bestv, 0);
    besti = __shfl_sync(0xffffffffu, besti, 0);

    const float thr = bestv - MARGIN;
    unsigned masks[10];
    int ncand = 0;
    #pragma unroll
    for (int j = 0; j < 10; j++) {
        masks[j] = __ballot_sync(0xffffffffu, v[j] >= thr);
        ncand += __popc(masks[j]);
    }

    int final_idx = besti;
    if (ncand > 1) {
        // exact fp32 rescore of every candidate; ascending col order, strict > => first-index ties
        const float* hrow = hidden + (size_t)r * K_DIM;
        float bexact = -INFINITY;
        int bidx = -1;
        for (int j = 0; j < 10; j++) {
            unsigned m = masks[j];
            while (m) {
                int l = __ffs(m) - 1;
                m &= m - 1;
                int col = l + 32 * j;
                const float* wrow = g_Wt + (size_t)(g * NVARS + col) * K_DIM;
                float s = 0.0f;
                for (int k = lane; k < K_DIM; k += 32)
                    s = fmaf(hrow[k], wrow[k], s);
                #pragma unroll
                for (int off = 16; off > 0; off >>= 1)
                    s += __shfl_xor_sync(0xffffffffu, s, off);
                s += bias[g * NVARS + col];
                if (s > bexact) { bexact = s; bidx = col; }
            }
        }
        final_idx = bidx;
    }

    if (lane == 0) {
        g_idx[r * 2 + g] = final_idx;
        atomicAdd(&g_counts[g * NVARS + final_idx], 1);
    }
}

// ---------------- kernel 6: gather codevectors ----------------
__global__ void gather_kernel(const float* __restrict__ cv, float* __restrict__ out) {
    int gid = blockIdx.x * blockDim.x + threadIdx.x;  // < M_DIM * 64 (float4 granularity)
    int r = gid >> 6;
    int q = gid & 63;
    int d = q * 4;
    const float* src;
    if (d < CVD) {
        int i0 = g_idx[r * 2];
        src = cv + ((size_t)i0 * CVD + d);
    } else {
        int i1 = g_idx[r * 2 + 1];
        src = cv + ((size_t)(NVARS + i1) * CVD + (d - CVD));
    }
    float4 val = *reinterpret_cast<const float4*>(src);
    *reinterpret_cast<float4*>(out + (size_t)r * 256 + d) = val;
}

// ---------------- kernel 7: perplexity ----------------
__global__ void ppl_kernel(float* __restrict__ out_scalar) {
    __shared__ float wsum[20];
    int tid = threadIdx.x;  // 640 threads
    float m = (float)g_counts[tid] * (1.0f / 16384.0f);
    float term = m * logf(m + 1e-7f);
    #pragma unroll
    for (int off = 16; off > 0; off >>= 1)
        term += __shfl_xor_sync(0xffffffffu, term, off);
    if ((tid & 31) == 0) wsum[tid >> 5] = term;
    __syncthreads();
    if (tid == 0) {
        float s0 = 0.0f, s1 = 0.0f;
        #pragma unroll
        for (int w = 0; w < 10; w++) s0 += wsum[w];
        #pragma unroll
        for (int w = 10; w < 20; w++) s1 += wsum[w];
        *out_scalar = expf(-s0) + expf(-s1);
    }
}

// ---------------- launch ----------------
extern "C" void kernel_launch(void* const* d_in, const int* in_sizes, int n_in,
                              void* d_out, int out_size) {
    const float* hidden = (const float*)d_in[0];   // (16,1024,4864) fp32
    const float* W      = (const float*)d_in[1];   // (4864,640) fp32
    const float* bias   = (const float*)d_in[2];   // (640,) fp32
    const float* cv     = (const float*)d_in[3];   // (1,640,128) fp32
    float* out = (float*)d_out;                    // out (16,1024,256) then perplexity scalar

    // 1. convert A to bf16 (exactly M*K/4 float4s -> 77824 blocks of 256)
    conv_a_kernel<<<(M_DIM * (K_DIM / 4)) / 256, 256>>>(hidden);
    // 2. transpose W (fp32 + bf16 copies)
    trans_w_kernel<<<dim3(N_DIM / 32, K_DIM / 32), dim3(32, 8)>>>(W);
    // 3. GEMM -> logits
    gemm_kernel<<<dim3(N_DIM / 128, M_DIM / 128), 256>>>(bias);
    // 4. zero histogram
    zero_counts_kernel<<<1, N_DIM>>>();
    // 5. argmax + exact rescue + counts
    argmax_kernel<<<(M_DIM * NGROUPS) / 8, 256>>>(hidden, bias);
    // 6. gather codevectors
    gather_kernel<<<(M_DIM * 64) / 256, 256>>>(cv, out);
    // 7. perplexity scalar at the tail of the output buffer
    ppl_kernel<<<1, N_DIM>>>(out + (out_size - 1));
}

// round 3
// speedup vs baseline: 1.3815x; 1.3815x over previous
#include <cuda_runtime.h>
#include <cuda_bf16.h>
#include <cstdint>
#include <math.h>

// Problem constants
#define M_DIM 16384          // B*S
#define K_DIM 4864           // IN_DIM
#define N_DIM 640            // G*V
#define NVARS 320
#define NGROUPS 2
#define CVD   128
#define MARGIN 0.02f

// GEMM tiling
#define BM 128
#define BN 128
#define BK 64
#define STAGES 3
#define NKT (K_DIM / BK)                 // 76

#define SM_A_STAGE (BM * BK * 2)         // 16 KB
#define SM_B_STAGE (BN * BK * 2)         // 16 KB
#define SM_STAGE   (SM_A_STAGE + SM_B_STAGE)
#define SM_TOTAL   (STAGES * SM_STAGE)   // 96 KB

// ---------------- scratch ----------------
__device__ __nv_bfloat16 g_Abf[(size_t)M_DIM * K_DIM];   // ~159 MB
__device__ __nv_bfloat16 g_Btbf[(size_t)N_DIM * K_DIM];  // ~6.2 MB  W^T bf16 [n][k]
__device__ float         g_Wt[(size_t)N_DIM * K_DIM];    // ~12.5 MB W^T fp32 [n][k]
__device__ float         g_logits[(size_t)M_DIM * N_DIM];// ~42 MB
__device__ int           g_idx[M_DIM * NGROUPS];
__device__ int           g_counts[N_DIM];

// ---------------- helpers ----------------
__device__ __forceinline__ uint32_t smem_u32(const void* p) {
    uint32_t a;
    asm("{ .reg .u64 t; cvta.to.shared.u64 t, %1; cvt.u32.u64 %0, t; }" : "=r"(a) : "l"(p));
    return a;
}
__device__ __forceinline__ void ldsm_x4(uint32_t* r, uint32_t addr) {
    asm volatile("ldmatrix.sync.aligned.m8n8.x4.shared.b16 {%0,%1,%2,%3}, [%4];"
        : "=r"(r[0]), "=r"(r[1]), "=r"(r[2]), "=r"(r[3]) : "r"(addr));
}

// ---------------- kernel 1: convert hidden_states fp32 -> bf16 ----------------
__global__ void conv_a_kernel(const float* __restrict__ A) {
    int i = blockIdx.x * blockDim.x + threadIdx.x;
    float4 v = reinterpret_cast<const float4*>(A)[i];
    __nv_bfloat162* o = reinterpret_cast<__nv_bfloat162*>(g_Abf) + (size_t)i * 2;
    o[0] = __floats2bfloat162_rn(v.x, v.y);
    o[1] = __floats2bfloat162_rn(v.z, v.w);
}

// ---------------- kernel 2: transpose W [K][N] -> Wt [N][K] (fp32 + bf16) ----------------
__global__ void trans_w_kernel(const float* __restrict__ W) {
    __shared__ float tile[32][33];
    int x = blockIdx.x * 32 + threadIdx.x;
    int y0 = blockIdx.y * 32;
    #pragma unroll
    for (int j = threadIdx.y; j < 32; j += 8)
        tile[j][threadIdx.x] = W[(size_t)(y0 + j) * N_DIM + x];
    __syncthreads();
    #pragma unroll
    for (int j = threadIdx.y; j < 32; j += 8) {
        int n = blockIdx.x * 32 + j;
        int k = y0 + threadIdx.x;
        float val = tile[threadIdx.x][j];
        g_Wt[(size_t)n * K_DIM + k] = val;
        g_Btbf[(size_t)n * K_DIM + k] = __float2bfloat16_rn(val);
    }
}

// ---------------- kernel 3: bf16 HMMA GEMM, logits = A @ W^T + b ----------------
// CTA 128x128, BK=64, 3-stage cp.async, ldmatrix fragment loads, 8 warps (4Mx2N),
// warp tile 32x64. 2 CTAs/SM.
__global__ __launch_bounds__(256, 2) void gemm_kernel(const float* __restrict__ bias) {
    extern __shared__ char smem[];
    const uint32_t su = smem_u32(smem);
    const int tid  = threadIdx.x;
    const int lane = tid & 31;
    const int warp = tid >> 5;
    const int wm = warp >> 1;        // 0..3
    const int wn = warp & 1;         // 0..1
    const int cta_m = blockIdx.y * BM;
    const int cta_n = blockIdx.x * BN;

    float acc[2][8][4];
    #pragma unroll
    for (int a = 0; a < 2; a++)
        #pragma unroll
        for (int b = 0; b < 8; b++)
            #pragma unroll
            for (int c = 0; c < 4; c++) acc[a][b][c] = 0.0f;

    // ---- fragment smem offsets (within a stage; swizzle: chunk ^= row&7) ----
    const int sw = lane & 7;
    // A: row = wm*32 + mt*16 + (lane&15); chunk = kk*2 + (lane>>4)
    uint32_t aOff[2];
    #pragma unroll
    for (int mt = 0; mt < 2; mt++)
        aOff[mt] = (uint32_t)((wm * 32 + mt * 16 + (lane & 15)) * 128);
    const int aChunkHi = lane >> 4;
    // B: row = wn*64 + p*16 + ((lane>>4)<<3) + (lane&7); chunk = kk*2 + ((lane>>3)&1)
    uint32_t bOff[4];
    #pragma unroll
    for (int p = 0; p < 4; p++)
        bOff[p] = (uint32_t)((wn * 64 + p * 16 + ((lane >> 4) << 3) + (lane & 7)) * 128);
    const int bChunkHi = (lane >> 3) & 1;

    // ---- stage loader: 16B cp.async, swizzled ----
    const __nv_bfloat16* Ag = g_Abf + (size_t)cta_m * K_DIM;
    const __nv_bfloat16* Bg = g_Btbf + (size_t)cta_n * K_DIM;
    auto load_stage = [&](int kt) {
        const int st = kt % STAGES;
        const int k0 = kt * BK;
        const uint32_t aB = su + st * SM_STAGE;
        const uint32_t bB = aB + SM_A_STAGE;
        #pragma unroll
        for (int i = 0; i < 4; i++) {
            int ch = tid + 256 * i;
            int row = ch >> 3, c = ch & 7;
            uint32_t dst = aB + row * 128 + ((c ^ (row & 7)) << 4);
            const void* src = Ag + (size_t)row * K_DIM + k0 + c * 8;
            asm volatile("cp.async.cg.shared.global [%0], [%1], 16;" :: "r"(dst), "l"(src));
        }
        #pragma unroll
        for (int i = 0; i < 4; i++) {
            int ch = tid + 256 * i;
            int row = ch >> 3, c = ch & 7;
            uint32_t dst = bB + row * 128 + ((c ^ (row & 7)) << 4);
            const void* src = Bg + (size_t)row * K_DIM + k0 + c * 8;
            asm volatile("cp.async.cg.shared.global [%0], [%1], 16;" :: "r"(dst), "l"(src));
        }
    };

    load_stage(0); asm volatile("cp.async.commit_group;");
    load_stage(1); asm volatile("cp.async.commit_group;");

    for (int kt = 0; kt < NKT; kt++) {
        if (kt + 1 < NKT) asm volatile("cp.async.wait_group 1;");
        else              asm volatile("cp.async.wait_group 0;");
        __syncthreads();

        if (kt + 2 < NKT) { load_stage(kt + 2); asm volatile("cp.async.commit_group;"); }

        const uint32_t stBase = su + (kt % STAGES) * SM_STAGE;
        const uint32_t bBase  = stBase + SM_A_STAGE;

        #pragma unroll
        for (int kk = 0; kk < 4; kk++) {
            uint32_t afr[2][4];
            #pragma unroll
            for (int mt = 0; mt < 2; mt++) {
                uint32_t addr = stBase + aOff[mt] + (((kk * 2 + aChunkHi) ^ sw) << 4);
                ldsm_x4(afr[mt], addr);
            }
            uint32_t bfr[4][4];   // [p] = {b0(2p), b1(2p), b0(2p+1), b1(2p+1)}
            #pragma unroll
            for (int p = 0; p < 4; p++) {
                uint32_t addr = bBase + bOff[p] + (((kk * 2 + bChunkHi) ^ sw) << 4);
                ldsm_x4(bfr[p], addr);
            }
            #pragma unroll
            for (int mt = 0; mt < 2; mt++) {
                #pragma unroll
                for (int p = 0; p < 4; p++) {
                    asm volatile(
                        "mma.sync.aligned.m16n8k16.row.col.f32.bf16.bf16.f32 "
                        "{%0,%1,%2,%3}, {%4,%5,%6,%7}, {%8,%9}, {%0,%1,%2,%3};\n"
                        : "+f"(acc[mt][2*p][0]), "+f"(acc[mt][2*p][1]),
                          "+f"(acc[mt][2*p][2]), "+f"(acc[mt][2*p][3])
                        : "r"(afr[mt][0]), "r"(afr[mt][1]), "r"(afr[mt][2]), "r"(afr[mt][3]),
                          "r"(bfr[p][0]), "r"(bfr[p][1]));
                    asm volatile(
                        "mma.sync.aligned.m16n8k16.row.col.f32.bf16.bf16.f32 "
                        "{%0,%1,%2,%3}, {%4,%5,%6,%7}, {%8,%9}, {%0,%1,%2,%3};\n"
                        : "+f"(acc[mt][2*p+1][0]), "+f"(acc[mt][2*p+1][1]),
                          "+f"(acc[mt][2*p+1][2]), "+f"(acc[mt][2*p+1][3])
                        : "r"(afr[mt][0]), "r"(afr[mt][1]), "r"(afr[mt][2]), "r"(afr[mt][3]),
                          "r"(bfr[p][2]), "r"(bfr[p][3]));
                }
            }
        }
        __syncthreads();
    }

    // epilogue: add bias, write logits. acc layout: c0/c1 at (row, col..col+1), c2/c3 at row+8
    const int g = lane >> 2;
    const int t = lane & 3;
    #pragma unroll
    for (int mt = 0; mt < 2; mt++) {
        int row = cta_m + wm * 32 + mt * 16 + g;
        #pragma unroll
        for (int nt = 0; nt < 8; nt++) {
            int col = cta_n + wn * 64 + nt * 8 + 2 * t;
            float2 bv = *reinterpret_cast<const float2*>(bias + col);
            float2 v0 = make_float2(acc[mt][nt][0] + bv.x, acc[mt][nt][1] + bv.y);
            float2 v1 = make_float2(acc[mt][nt][2] + bv.x, acc[mt][nt][3] + bv.y);
            *reinterpret_cast<float2*>(g_logits + (size_t)row * N_DIM + col) = v0;
            *reinterpret_cast<float2*>(g_logits + (size_t)(row + 8) * N_DIM + col) = v1;
        }
    }
}

// ---------------- kernel 4: zero counts ----------------
__global__ void zero_counts_kernel() { g_counts[threadIdx.x] = 0; }

// ---------------- kernel 5: argmax + exact fp32 rescue + histogram ----------------
__global__ __launch_bounds__(256) void argmax_kernel(const float* __restrict__ hidden,
                                                     const float* __restrict__ bias) {
    const int lane = threadIdx.x & 31;
    const int gw = blockIdx.x * 8 + (threadIdx.x >> 5);
    const int r = gw >> 1;
    const int g = gw & 1;
    const float* base = g_logits + (size_t)r * N_DIM + g * NVARS;

    float v[10];
    float bestv = -INFINITY;
    int besti = 0x7fffffff;
    #pragma unroll
    for (int j = 0; j < 10; j++) {
        v[j] = base[lane + 32 * j];
        int idx = lane + 32 * j;
        if (v[j] > bestv) { bestv = v[j]; besti = idx; }
    }
    #pragma unroll
    for (int off = 16; off > 0; off >>= 1) {
        float ov = __shfl_down_sync(0xffffffffu, bestv, off);
        int   oi = __shfl_down_sync(0xffffffffu, besti, off);
        if (ov > bestv || (ov == bestv && oi < besti)) { bestv = ov; besti = oi; }
    }
    bestv = __shfl_sync(0xffffffffu, bestv, 0);
    besti = __shfl_sync(0xffffffffu, besti, 0);

    const float thr = bestv - MARGIN;
    unsigned masks[10];
    int ncand = 0;
    #pragma unroll
    for (int j = 0; j < 10; j++) {
        masks[j] = __ballot_sync(0xffffffffu, v[j] >= thr);
        ncand += __popc(masks[j]);
    }

    int final_idx = besti;
    if (ncand > 1) {
        const float* hrow = hidden + (size_t)r * K_DIM;
        float bexact = -INFINITY;
        int bidx = -1;
        for (int j = 0; j < 10; j++) {
            unsigned m = masks[j];
            while (m) {
                int l = __ffs(m) - 1;
                m &= m - 1;
                int col = l + 32 * j;
                const float* wrow = g_Wt + (size_t)(g * NVARS + col) * K_DIM;
                float s = 0.0f;
                for (int k = lane; k < K_DIM; k += 32)
                    s = fmaf(hrow[k], wrow[k], s);
                #pragma unroll
                for (int off = 16; off > 0; off >>= 1)
                    s += __shfl_xor_sync(0xffffffffu, s, off);
                s += bias[g * NVARS + col];
                if (s > bexact) { bexact = s; bidx = col; }
            }
        }
        final_idx = bidx;
    }

    if (lane == 0) {
        g_idx[r * 2 + g] = final_idx;
        atomicAdd(&g_counts[g * NVARS + final_idx], 1);
    }
}

// ---------------- kernel 6: gather codevectors ----------------
__global__ void gather_kernel(const float* __restrict__ cv, float* __restrict__ out) {
    int gid = blockIdx.x * blockDim.x + threadIdx.x;
    int r = gid >> 6;
    int q = gid & 63;
    int d = q * 4;
    const float* src;
    if (d < CVD) {
        int i0 = g_idx[r * 2];
        src = cv + ((size_t)i0 * CVD + d);
    } else {
        int i1 = g_idx[r * 2 + 1];
        src = cv + ((size_t)(NVARS + i1) * CVD + (d - CVD));
    }
    float4 val = *reinterpret_cast<const float4*>(src);
    *reinterpret_cast<float4*>(out + (size_t)r * 256 + d) = val;
}

// ---------------- kernel 7: perplexity ----------------
__global__ void ppl_kernel(float* __restrict__ out_scalar) {
    __shared__ float wsum[20];
    int tid = threadIdx.x;
    float m = (float)g_counts[tid] * (1.0f / 16384.0f);
    float term = m * logf(m + 1e-7f);
    #pragma unroll
    for (int off = 16; off > 0; off >>= 1)
        term += __shfl_xor_sync(0xffffffffu, term, off);
    if ((tid & 31) == 0) wsum[tid >> 5] = term;
    __syncthreads();
    if (tid == 0) {
        float s0 = 0.0f, s1 = 0.0f;
        #pragma unroll
        for (int w = 0; w < 10; w++) s0 += wsum[w];
        #pragma unroll
        for (int w = 10; w < 20; w++) s1 += wsum[w];
        *out_scalar = expf(-s0) + expf(-s1);
    }
}

// ---------------- launch ----------------
extern "C" void kernel_launch(void* const* d_in, const int* in_sizes, int n_in,
                              void* d_out, int out_size) {
    const float* hidden = (const float*)d_in[0];
    const float* W      = (const float*)d_in[1];
    const float* bias   = (const float*)d_in[2];
    const float* cv     = (const float*)d_in[3];
    float* out = (float*)d_out;

    cudaFuncSetAttribute(gemm_kernel, cudaFuncAttributeMaxDynamicSharedMemorySize, SM_TOTAL);

    conv_a_kernel<<<(M_DIM * (K_DIM / 4)) / 256, 256>>>(hidden);
    trans_w_kernel<<<dim3(N_DIM / 32, K_DIM / 32), dim3(32, 8)>>>(W);
    gemm_kernel<<<dim3(N_DIM / BN, M_DIM / BM), 256, SM_TOTAL>>>(bias);
    zero_counts_kernel<<<1, N_DIM>>>();
    argmax_kernel<<<(M_DIM * NGROUPS) / 8, 256>>>(hidden, bias);
    gather_kernel<<<(M_DIM * 64) / 256, 256>>>(cv, out);
    ppl_kernel<<<1, N_DIM>>>(out + (out_size - 1));
}